// round 1
// baseline (speedup 1.0000x reference)
#include <cuda_runtime.h>
#include <stdint.h>

// ---------------- problem constants ----------------
#define USER_N 100000
#define ITEM_N 50000
#define TAG_N  20000
#define NADJ   (USER_N + ITEM_N)   // 150000
#define MTAG   (ITEM_N + TAG_N)    // 70000
#define EADJ   2000000
#define ETAG   1000000
#define ESOC   1000000
#define ETOT   (EADJ + ETAG + ESOC)  // 4,000,000

// rows are D=64 floats = 16 float4 per node
#define R4 16

// ---------------- device scratch (static globals: no runtime alloc) ----------------
__device__ float4 g_lat[NADJ * R4];      // 38.4 MB
__device__ float4 g_taglat[MTAG * R4];   // 17.9 MB
__device__ float4 g_tem[NADJ * R4];      // 38.4 MB
__device__ float4 g_tg[MTAG * R4];       // 17.9 MB
__device__ float4 g_soc[USER_N * R4];    // 25.6 MB
__device__ float  g_mv[ETOT];            // masked edge values: adj | tag | soc

// ---------------- threefry-2x32-20 (JAX-exact) ----------------
__device__ __forceinline__ uint32_t d_rotl(uint32_t v, int r) {
    return __funnelshift_l(v, v, r);
}

// returns o0 ^ o1 of threefry2x32(key=(K1,K2), x=(0, ctr))  [partitionable 32-bit bits]
__device__ __forceinline__ uint32_t tf_bits(uint32_t K1, uint32_t K2, uint32_t ctr) {
    uint32_t ks2 = K1 ^ K2 ^ 0x1BD11BDAu;
    uint32_t x0 = K1;          // 0 + ks0
    uint32_t x1 = ctr + K2;    // ctr + ks1
#define TF_R4(a,b,c,d)                                        \
    x0 += x1; x1 = d_rotl(x1,a); x1 ^= x0;                    \
    x0 += x1; x1 = d_rotl(x1,b); x1 ^= x0;                    \
    x0 += x1; x1 = d_rotl(x1,c); x1 ^= x0;                    \
    x0 += x1; x1 = d_rotl(x1,d); x1 ^= x0;
    TF_R4(13,15,26,6)   x0 += K2;  x1 += ks2 + 1u;
    TF_R4(17,29,16,24)  x0 += ks2; x1 += K1  + 2u;
    TF_R4(13,15,26,6)   x0 += K1;  x1 += K2  + 3u;
    TF_R4(17,29,16,24)  x0 += K2;  x1 += ks2 + 4u;
    TF_R4(13,15,26,6)   x0 += ks2; x1 += K1  + 5u;
#undef TF_R4
    return x0 ^ x1;
}

// host version (for fold_in key derivation)
static inline uint32_t h_rotl(uint32_t v, int r) { return (v << r) | (v >> (32 - r)); }
static void h_threefry(uint32_t K1, uint32_t K2, uint32_t x0, uint32_t x1,
                       uint32_t* o0, uint32_t* o1) {
    uint32_t ks[3] = {K1, K2, K1 ^ K2 ^ 0x1BD11BDAu};
    static const int rots[2][4] = {{13,15,26,6},{17,29,16,24}};
    x0 += ks[0]; x1 += ks[1];
    for (int g = 0; g < 5; ++g) {
        const int* rr = rots[g & 1];
        for (int j = 0; j < 4; ++j) { x0 += x1; x1 = h_rotl(x1, rr[j]); x1 ^= x0; }
        x0 += ks[(g + 1) % 3];
        x1 += ks[(g + 2) % 3] + (uint32_t)(g + 1);
    }
    *o0 = x0; *o1 = x1;
}

// ---------------- helpers ----------------
__device__ __forceinline__ float4 leaky4(float4 h) {
    h.x = h.x >= 0.f ? h.x : 0.5f * h.x;
    h.y = h.y >= 0.f ? h.y : 0.5f * h.y;
    h.z = h.z >= 0.f ? h.z : 0.5f * h.z;
    h.w = h.w >= 0.f ? h.w : 0.5f * h.w;
    return h;
}

// ---------------- kernels ----------------

// lat = concat(u, i); out = lat; taglat = concat(i, t). grid*block == NADJ*R4
__global__ void init_kernel(const float4* __restrict__ u4,
                            const float4* __restrict__ i4,
                            const float4* __restrict__ t4,
                            float4* __restrict__ out) {
    unsigned idx = blockIdx.x * blockDim.x + threadIdx.x;  // < NADJ*R4
    float4 s = (idx < USER_N * R4) ? __ldg(u4 + idx) : __ldg(i4 + idx - USER_N * R4);
    g_lat[idx] = s;
    out[idx]   = s;
    if (idx < MTAG * R4) {
        g_taglat[idx] = (idx < ITEM_N * R4) ? __ldg(i4 + idx)
                                            : __ldg(t4 + idx - ITEM_N * R4);
    }
}

// Per-edge dropout masks (threefry) + zero the spmm accumulators.
// grid*block == ETOT (4,000,000 threads)
__global__ void mask_zero_kernel(const float* __restrict__ av,
                                 const float* __restrict__ tv,
                                 const float* __restrict__ sv,
                                 uint32_t ka1, uint32_t ka2,
                                 uint32_t kt1, uint32_t kt2,
                                 uint32_t ku1, uint32_t ku2) {
    unsigned tid = blockIdx.x * blockDim.x + threadIdx.x;

    // zero accumulators (tem | tg | soc), grid-stride
    const unsigned NT = NADJ * R4, NG = MTAG * R4, NS = USER_N * R4;
    const float4 z = make_float4(0.f, 0.f, 0.f, 0.f);
    for (unsigned k = tid; k < NT + NG + NS; k += ETOT) {
        if (k < NT)           g_tem[k] = z;
        else if (k < NT + NG) g_tg[k - NT] = z;
        else                  g_soc[k - NT - NG] = z;
    }

    const float* v; uint32_t k1, k2; unsigned e, off;
    if (tid < EADJ)              { v = av; k1 = ka1; k2 = ka2; e = tid;               off = 0; }
    else if (tid < EADJ + ETAG)  { v = tv; k1 = kt1; k2 = kt2; e = tid - EADJ;        off = EADJ; }
    else                         { v = sv; k1 = ku1; k2 = ku2; e = tid - EADJ - ETAG; off = EADJ + ETAG; }

    uint32_t bits = tf_bits(k1, k2, e);
    float u = __uint_as_float((bits >> 9) | 0x3f800000u) - 1.0f;   // [0,1) as in jax
    float keep = floorf(u + 0.9f);                                 // floor(u + KEEP)
    g_mv[off + e] = (__ldg(v + e) * keep) * (float)(1.0 / 0.9);
}

// Fused 3-graph SPMM. 16 edges/block (2 edges/warp, 16 lanes x float4 per edge).
#define B_ADJ (EADJ / 16)   // 125000
#define B_TAG (ETAG / 16)   //  62500
#define B_SOC (ESOC / 16)   //  62500
__global__ void spmm_kernel(const int* __restrict__ ar, const int* __restrict__ ac,
                            const int* __restrict__ tr, const int* __restrict__ tc,
                            const int* __restrict__ sr, const int* __restrict__ sc) {
    unsigned bid = blockIdx.x;
    const int *rows, *cols; const float* mv; float4* outb; int mode; unsigned wb;
    if (bid < B_ADJ)               { rows = ar; cols = ac; mv = g_mv;              outb = g_tem; mode = 0; wb = bid; }
    else if (bid < B_ADJ + B_TAG)  { rows = tr; cols = tc; mv = g_mv + EADJ;       outb = g_tg;  mode = 1; wb = bid - B_ADJ; }
    else                           { rows = sr; cols = sc; mv = g_mv + EADJ + ETAG; outb = g_soc; mode = 2; wb = bid - B_ADJ - B_TAG; }

    unsigned lane  = threadIdx.x & 31u;
    unsigned warp  = threadIdx.x >> 5;
    unsigned e     = (wb * 8u + warp) * 2u + (lane >> 4);
    unsigned chunk = lane & 15u;

    float v = __ldg(mv + e);
    if (v == 0.f) return;               // dropped edge: skip gather + scatter
    int r = __ldg(rows + e);
    int c = __ldg(cols + e);

    const float4* x;
    if (mode == 1)
        x = (c < ITEM_N) ? (g_lat + (unsigned)(USER_N + c) * R4)
                         : (g_taglat + (unsigned)c * R4);
    else
        x = g_lat + (unsigned)c * R4;

    float4 xv = __ldg(x + chunk);
    float4 cv = make_float4(v * xv.x, v * xv.y, v * xv.z, v * xv.w);
    float4* dst = outb + (unsigned)r * R4 + chunk;
    asm volatile("red.global.add.v4.f32 [%0], {%1,%2,%3,%4};"
                 :: "l"(dst), "f"(cv.x), "f"(cv.y), "f"(cv.z), "f"(cv.w)
                 : "memory");
}

// lat = leaky(tem) + (user? leaky(soc) : leaky(tg)); out += lat; taglat = leaky(tg)
// grid*block == NADJ*R4
__global__ void combine_kernel(float4* __restrict__ out) {
    unsigned idx = blockIdx.x * blockDim.x + threadIdx.x;  // < NADJ*R4
    float4 t = leaky4(g_tem[idx]);
    float4 o;
    if (idx < USER_N * R4) {
        float4 s = leaky4(g_soc[idx]);
        o = make_float4(t.x + s.x, t.y + s.y, t.z + s.z, t.w + s.w);
    } else {
        float4 gv = leaky4(g_tg[idx - USER_N * R4]);
        o = make_float4(t.x + gv.x, t.y + gv.y, t.z + gv.z, t.w + gv.w);
    }
    g_lat[idx] = o;
    float4 a = out[idx];
    a.x += o.x; a.y += o.y; a.z += o.z; a.w += o.w;
    out[idx] = a;
    if (idx < MTAG * R4)
        g_taglat[idx] = leaky4(g_tg[idx]);
}

// ---------------- launch ----------------
extern "C" void kernel_launch(void* const* d_in, const int* in_sizes, int n_in,
                              void* d_out, int out_size) {
    const float4* uE = (const float4*)d_in[0];
    const float4* iE = (const float4*)d_in[1];
    const float4* tE = (const float4*)d_in[2];
    const int*   ar = (const int*)d_in[3];
    const int*   ac = (const int*)d_in[4];
    const float* av = (const float*)d_in[5];
    const int*   tr = (const int*)d_in[6];
    const int*   tc = (const int*)d_in[7];
    const float* tv = (const float*)d_in[8];
    const int*   sr = (const int*)d_in[9];
    const int*   sc = (const int*)d_in[10];
    const float* sv = (const float*)d_in[11];
    float4* out = (float4*)d_out;

    // jax.random.key(42) -> (0, 42); fold_in(key, j) = threefry2x32(key, (0, j))
    uint32_t fk[6][2];
    for (uint32_t j = 0; j < 6; ++j)
        h_threefry(0u, 42u, 0u, j, &fk[j][0], &fk[j][1]);

    const int TB = 256;
    const int INIT_G = (NADJ * R4) / TB;   // 9375
    const int MASK_G = ETOT / TB;          // 15625
    const int SPMM_G = B_ADJ + B_TAG + B_SOC;  // 250000
    const int COMB_G = (NADJ * R4) / TB;   // 9375

    init_kernel<<<INIT_G, TB>>>(uE, iE, tE, out);
    for (int L = 0; L < 2; ++L) {
        mask_zero_kernel<<<MASK_G, TB>>>(av, tv, sv,
                                         fk[3 * L][0],     fk[3 * L][1],
                                         fk[3 * L + 1][0], fk[3 * L + 1][1],
                                         fk[3 * L + 2][0], fk[3 * L + 2][1]);
        spmm_kernel<<<SPMM_G, TB>>>(ar, ac, tr, tc, sr, sc);
        combine_kernel<<<COMB_G, TB>>>(out);
    }
}

// round 2
// speedup vs baseline: 1.2075x; 1.2075x over previous
#include <cuda_runtime.h>
#include <stdint.h>

// ---------------- problem constants ----------------
#define USER_N 100000
#define ITEM_N 50000
#define TAG_N  20000
#define NADJ   (USER_N + ITEM_N)   // 150000
#define MTAG   (ITEM_N + TAG_N)    // 70000
#define EADJ   2000000
#define ETAG   1000000
#define ESOC   1000000
#define ETOT   (EADJ + ETAG + ESOC)  // 4,000,000
#define R4     16                    // D=64 floats = 16 float4
#define TB     256

#define MASKB  (ETOT / TB)           // 15625 blocks of mask work
#define INITB  ((NADJ * R4) / TB)    // 9375 blocks of init/combine work
#define EPB    128                   // edges per spmm block
#define A_BLK  (EADJ / EPB)                  // 15625
#define T_BLK  ((ETAG + EPB - 1) / EPB)      // 7813
#define S_BLK  ((ESOC + EPB - 1) / EPB)      // 7813
#define SPMMB  (A_BLK + T_BLK + S_BLK)       // 31251

// ---------------- device scratch ----------------
__device__ float4 g_lat[NADJ * R4];          // 38.4 MB
__device__ float4 g_taglat[MTAG * R4];       // 17.9 MB
__device__ float4 g_tem[NADJ * R4];          // 38.4 MB
__device__ float4 g_tg[2][MTAG * R4];        // 35.8 MB (double-buffered: no zero-race)
__device__ float4 g_soc[USER_N * R4];        // 25.6 MB
__device__ float  g_mv[2][ETOT];             // 32 MB masked edge values (per layer)

// ---------------- threefry-2x32-20 (JAX partitionable, bit-exact) ----------------
__device__ __forceinline__ uint32_t d_rotl(uint32_t v, int r) {
    return __funnelshift_l(v, v, r);
}
__device__ __forceinline__ uint32_t tf_bits(uint32_t K1, uint32_t K2, uint32_t ctr) {
    uint32_t ks2 = K1 ^ K2 ^ 0x1BD11BDAu;
    uint32_t x0 = K1;          // 0 + ks0
    uint32_t x1 = ctr + K2;    // ctr + ks1
#define TF_R4(a,b,c,d)                                        \
    x0 += x1; x1 = d_rotl(x1,a); x1 ^= x0;                    \
    x0 += x1; x1 = d_rotl(x1,b); x1 ^= x0;                    \
    x0 += x1; x1 = d_rotl(x1,c); x1 ^= x0;                    \
    x0 += x1; x1 = d_rotl(x1,d); x1 ^= x0;
    TF_R4(13,15,26,6)   x0 += K2;  x1 += ks2 + 1u;
    TF_R4(17,29,16,24)  x0 += ks2; x1 += K1  + 2u;
    TF_R4(13,15,26,6)   x0 += K1;  x1 += K2  + 3u;
    TF_R4(17,29,16,24)  x0 += K2;  x1 += ks2 + 4u;
    TF_R4(13,15,26,6)   x0 += ks2; x1 += K1  + 5u;
#undef TF_R4
    return x0 ^ x1;
}

static inline uint32_t h_rotl(uint32_t v, int r) { return (v << r) | (v >> (32 - r)); }
static void h_threefry(uint32_t K1, uint32_t K2, uint32_t x0, uint32_t x1,
                       uint32_t* o0, uint32_t* o1) {
    uint32_t ks[3] = {K1, K2, K1 ^ K2 ^ 0x1BD11BDAu};
    static const int rots[2][4] = {{13,15,26,6},{17,29,16,24}};
    x0 += ks[0]; x1 += ks[1];
    for (int g = 0; g < 5; ++g) {
        const int* rr = rots[g & 1];
        for (int j = 0; j < 4; ++j) { x0 += x1; x1 = h_rotl(x1, rr[j]); x1 ^= x0; }
        x0 += ks[(g + 1) % 3];
        x1 += ks[(g + 2) % 3] + (uint32_t)(g + 1);
    }
    *o0 = x0; *o1 = x1;
}

// ---------------- helpers ----------------
__device__ __forceinline__ float4 leaky4(float4 h) {
    h.x = h.x >= 0.f ? h.x : 0.5f * h.x;
    h.y = h.y >= 0.f ? h.y : 0.5f * h.y;
    h.z = h.z >= 0.f ? h.z : 0.5f * h.z;
    h.w = h.w >= 0.f ? h.w : 0.5f * h.w;
    return h;
}

// per-edge dropout mask -> masked value, written to g_mv[layer]
__device__ __forceinline__ void mask_edge(unsigned tid, float* __restrict__ mvOut,
                                          const float* __restrict__ av,
                                          const float* __restrict__ tv,
                                          const float* __restrict__ sv,
                                          uint32_t ka1, uint32_t ka2,
                                          uint32_t kt1, uint32_t kt2,
                                          uint32_t ku1, uint32_t ku2) {
    const float* v; uint32_t k1, k2; unsigned e, off;
    if (tid < EADJ)              { v = av; k1 = ka1; k2 = ka2; e = tid;               off = 0; }
    else if (tid < EADJ + ETAG)  { v = tv; k1 = kt1; k2 = kt2; e = tid - EADJ;        off = EADJ; }
    else                         { v = sv; k1 = ku1; k2 = ku2; e = tid - EADJ - ETAG; off = EADJ + ETAG; }
    uint32_t bits = tf_bits(k1, k2, e);
    float u = __uint_as_float((bits >> 9) | 0x3f800000u) - 1.0f;   // [0,1) as in jax
    float keep = floorf(u + 0.9f);
    mvOut[off + e] = (__ldg(v + e) * keep) * (float)(1.0 / 0.9);
}

// ---------------- kernels ----------------

// Blocks [0, MASKB): layer-0 mask.  Blocks [MASKB, MASKB+INITB): init lat/out/taglat + zero accumulators.
__global__ void prep_kernel(const float4* __restrict__ u4,
                            const float4* __restrict__ i4,
                            const float4* __restrict__ t4,
                            float4* __restrict__ out,
                            uint32_t ka1, uint32_t ka2, uint32_t kt1, uint32_t kt2,
                            uint32_t ku1, uint32_t ku2,
                            const float* __restrict__ av,
                            const float* __restrict__ tv,
                            const float* __restrict__ sv) {
    if (blockIdx.x < MASKB) {
        unsigned tid = blockIdx.x * TB + threadIdx.x;
        mask_edge(tid, g_mv[0], av, tv, sv, ka1, ka2, kt1, kt2, ku1, ku2);
        return;
    }
    unsigned idx = (blockIdx.x - MASKB) * TB + threadIdx.x;   // < NADJ*R4
    float4 s = (idx < USER_N * R4) ? __ldg(u4 + idx) : __ldg(i4 + idx - USER_N * R4);
    g_lat[idx] = s;
    out[idx]   = s;
    if (idx < MTAG * R4)
        g_taglat[idx] = (idx < ITEM_N * R4) ? __ldg(i4 + idx) : __ldg(t4 + idx - ITEM_N * R4);
    const float4 z = make_float4(0.f, 0.f, 0.f, 0.f);
    g_tem[idx] = z;
    // zero tg[0], tg[1], soc  (2*MTAG + USER_N)*R4 = 3,840,000 float4, stride NADJ*R4
    const unsigned NG = MTAG * R4, NS = USER_N * R4;
    for (unsigned k = idx; k < 2 * NG + NS; k += (unsigned)NADJ * R4) {
        if (k < NG)               g_tg[0][k] = z;
        else if (k < 2 * NG)      g_tg[1][k - NG] = z;
        else                      g_soc[k - 2 * NG] = z;
    }
}

// Fused: blocks [0, nMask) compute next layer's mask (pure ALU);
// blocks [nMask, nMask+SPMMB) run the 3-graph SPMM for the current layer (memory-bound).
__global__ void work_kernel(int nMask, int maskLayer, int spmmLayer,
                            uint32_t ka1, uint32_t ka2, uint32_t kt1, uint32_t kt2,
                            uint32_t ku1, uint32_t ku2,
                            const float* __restrict__ av,
                            const float* __restrict__ tv,
                            const float* __restrict__ sv,
                            const int* __restrict__ ar, const int* __restrict__ ac,
                            const int* __restrict__ tr, const int* __restrict__ tc,
                            const int* __restrict__ sr, const int* __restrict__ sc) {
    if ((int)blockIdx.x < nMask) {
        unsigned tid = blockIdx.x * TB + threadIdx.x;
        mask_edge(tid, g_mv[maskLayer], av, tv, sv, ka1, ka2, kt1, kt2, ku1, ku2);
        return;
    }
    unsigned sbid = blockIdx.x - nMask;
    const float* mvIn = g_mv[spmmLayer];
    const int *rows, *cols; const float* mv; float4* outb; int mode; unsigned wb, Eg;
    if (sbid < A_BLK) {
        rows = ar; cols = ac; mv = mvIn;               outb = g_tem;            mode = 0; wb = sbid;                 Eg = EADJ;
    } else if (sbid < A_BLK + T_BLK) {
        rows = tr; cols = tc; mv = mvIn + EADJ;        outb = g_tg[spmmLayer];  mode = 1; wb = sbid - A_BLK;         Eg = ETAG;
    } else {
        rows = sr; cols = sc; mv = mvIn + EADJ + ETAG; outb = g_soc;            mode = 2; wb = sbid - A_BLK - T_BLK; Eg = ESOC;
    }
    unsigned lane  = threadIdx.x & 31u;
    unsigned warp  = threadIdx.x >> 5;
    unsigned chunk = lane & 15u;
    unsigned ebase = wb * EPB + warp * 2u + (lane >> 4);
#pragma unroll
    for (int i = 0; i < EPB / 16; ++i) {
        unsigned e = ebase + (unsigned)i * 16u;
        if (e >= Eg) break;
        float v = __ldg(mv + e);
        if (v != 0.f) {                          // dropped edge: skip gather + scatter
            int r = __ldg(rows + e);
            int c = __ldg(cols + e);
            const float4* x;
            if (mode == 1)
                x = (c < ITEM_N) ? (g_lat + (unsigned)(USER_N + c) * R4)
                                 : (g_taglat + (unsigned)c * R4);
            else
                x = g_lat + (unsigned)c * R4;
            float4 xv = __ldg(x + chunk);
            float4* dst = outb + (unsigned)r * R4 + chunk;
            asm volatile("red.global.add.v4.f32 [%0], {%1,%2,%3,%4};"
                         :: "l"(dst), "f"(v * xv.x), "f"(v * xv.y),
                            "f"(v * xv.z), "f"(v * xv.w)
                         : "memory");
        }
    }
}

// MID=true (layer 0): also write lat/taglat for next layer and zero tem/soc for layer 1.
// MID=false (final): only accumulate into out.
template <bool MID>
__global__ void combine_kernel(float4* __restrict__ out, int layer) {
    unsigned idx = blockIdx.x * TB + threadIdx.x;   // < NADJ*R4
    const float4* tg = g_tg[layer];
    const float4 z = make_float4(0.f, 0.f, 0.f, 0.f);
    float4 t = leaky4(g_tem[idx]);
    float4 o;
    if (idx < USER_N * R4) {
        float4 s = leaky4(g_soc[idx]);
        o = make_float4(t.x + s.x, t.y + s.y, t.z + s.z, t.w + s.w);
        if (MID) g_soc[idx] = z;
    } else {
        float4 gv = leaky4(tg[idx - USER_N * R4]);
        o = make_float4(t.x + gv.x, t.y + gv.y, t.z + gv.z, t.w + gv.w);
    }
    if (MID) { g_tem[idx] = z; g_lat[idx] = o; }
    float4 a = out[idx];
    a.x += o.x; a.y += o.y; a.z += o.z; a.w += o.w;
    out[idx] = a;
    if (MID && idx < MTAG * R4)
        g_taglat[idx] = leaky4(tg[idx]);
}

// ---------------- launch ----------------
extern "C" void kernel_launch(void* const* d_in, const int* in_sizes, int n_in,
                              void* d_out, int out_size) {
    const float4* uE = (const float4*)d_in[0];
    const float4* iE = (const float4*)d_in[1];
    const float4* tE = (const float4*)d_in[2];
    const int*   ar = (const int*)d_in[3];
    const int*   ac = (const int*)d_in[4];
    const float* av = (const float*)d_in[5];
    const int*   tr = (const int*)d_in[6];
    const int*   tc = (const int*)d_in[7];
    const float* tv = (const float*)d_in[8];
    const int*   sr = (const int*)d_in[9];
    const int*   sc = (const int*)d_in[10];
    const float* sv = (const float*)d_in[11];
    float4* out = (float4*)d_out;

    // jax.random.key(42) -> (0, 42); fold_in(key, j) = threefry2x32(key, (0, j))
    uint32_t fk[6][2];
    for (uint32_t j = 0; j < 6; ++j)
        h_threefry(0u, 42u, 0u, j, &fk[j][0], &fk[j][1]);

    // mask0 || (init + zero)
    prep_kernel<<<MASKB + INITB, TB>>>(uE, iE, tE, out,
                                       fk[0][0], fk[0][1], fk[1][0], fk[1][1],
                                       fk[2][0], fk[2][1], av, tv, sv);
    // mask1 || spmm0
    work_kernel<<<MASKB + SPMMB, TB>>>(MASKB, /*maskLayer=*/1, /*spmmLayer=*/0,
                                       fk[3][0], fk[3][1], fk[4][0], fk[4][1],
                                       fk[5][0], fk[5][1],
                                       av, tv, sv, ar, ac, tr, tc, sr, sc);
    // combine0 (+ zero tem/soc for layer 1)
    combine_kernel<true><<<INITB, TB>>>(out, 0);
    // spmm1 (no mask work left)
    work_kernel<<<SPMMB, TB>>>(0, 1, 1,
                               0u, 0u, 0u, 0u, 0u, 0u,
                               av, tv, sv, ar, ac, tr, tc, sr, sc);
    // combine1 (final)
    combine_kernel<false><<<INITB, TB>>>(out, 1);
}

// round 4
// speedup vs baseline: 1.2353x; 1.0231x over previous
#include <cuda_runtime.h>
#include <stdint.h>

// ---------------- problem constants ----------------
#define USER_N 100000
#define ITEM_N 50000
#define TAG_N  20000
#define NADJ   (USER_N + ITEM_N)   // 150000
#define MTAG   (ITEM_N + TAG_N)    // 70000
#define EADJ   2000000
#define ETAG   1000000
#define ESOC   1000000
#define ETOT   (EADJ + ETAG + ESOC)  // 4,000,000
#define R4     16                    // D=64 floats = 16 float4
#define TB     256

#define INITB  ((NADJ * R4) / TB)    // 9375 init/combine blocks
#define EPB    128                   // edges per spmm block (8 per 16-lane slot)
#define NE     (EPB / 16)            // 8 edges per thread-slot
#define A_BLK  (EADJ / EPB)                  // 15625 (exact)
#define T_BLK  ((ETAG + EPB - 1) / EPB)      // 7813
#define S_BLK  ((ESOC + EPB - 1) / EPB)      // 7813

// mask block split: P1 covers [0, 7813*256) = [0, 2000128) ⊇ adj edges
#define MB_P1  7813
#define MB_P2  (ETOT / TB - MB_P1)   // 7812, covers [2000128, 4000000)
#define MB_ALL (ETOT / TB)           // 15625

// ---------------- device scratch ----------------
__device__ float4 g_lat[NADJ * R4];
__device__ float4 g_taglat[MTAG * R4];
__device__ float4 g_tem[NADJ * R4];
__device__ float4 g_tg[2][MTAG * R4];     // double-buffered (no zero-race)
__device__ float4 g_soc[USER_N * R4];
__device__ float  g_mv[2][ETOT];          // masked edge values per layer

// ---------------- threefry-2x32-20 (JAX partitionable, bit-exact) ----------------
__device__ __forceinline__ uint32_t d_rotl(uint32_t v, int r) {
    return __funnelshift_l(v, v, r);
}
__device__ __forceinline__ uint32_t tf_bits(uint32_t K1, uint32_t K2, uint32_t ctr) {
    uint32_t ks2 = K1 ^ K2 ^ 0x1BD11BDAu;
    uint32_t x0 = K1;
    uint32_t x1 = ctr + K2;
#define TF_R4(a,b,c,d)                                        \
    x0 += x1; x1 = d_rotl(x1,a); x1 ^= x0;                    \
    x0 += x1; x1 = d_rotl(x1,b); x1 ^= x0;                    \
    x0 += x1; x1 = d_rotl(x1,c); x1 ^= x0;                    \
    x0 += x1; x1 = d_rotl(x1,d); x1 ^= x0;
    TF_R4(13,15,26,6)   x0 += K2;  x1 += ks2 + 1u;
    TF_R4(17,29,16,24)  x0 += ks2; x1 += K1  + 2u;
    TF_R4(13,15,26,6)   x0 += K1;  x1 += K2  + 3u;
    TF_R4(17,29,16,24)  x0 += K2;  x1 += ks2 + 4u;
    TF_R4(13,15,26,6)   x0 += ks2; x1 += K1  + 5u;
#undef TF_R4
    return x0 ^ x1;
}

static inline uint32_t h_rotl(uint32_t v, int r) { return (v << r) | (v >> (32 - r)); }
static void h_threefry(uint32_t K1, uint32_t K2, uint32_t x0, uint32_t x1,
                       uint32_t* o0, uint32_t* o1) {
    uint32_t ks[3] = {K1, K2, K1 ^ K2 ^ 0x1BD11BDAu};
    static const int rots[2][4] = {{13,15,26,6},{17,29,16,24}};
    x0 += ks[0]; x1 += ks[1];
    for (int g = 0; g < 5; ++g) {
        const int* rr = rots[g & 1];
        for (int j = 0; j < 4; ++j) { x0 += x1; x1 = h_rotl(x1, rr[j]); x1 ^= x0; }
        x0 += ks[(g + 1) % 3];
        x1 += ks[(g + 2) % 3] + (uint32_t)(g + 1);
    }
    *o0 = x0; *o1 = x1;
}

// ---------------- helpers ----------------
__device__ __forceinline__ float4 leaky4(float4 h) {
    h.x = h.x >= 0.f ? h.x : 0.5f * h.x;
    h.y = h.y >= 0.f ? h.y : 0.5f * h.y;
    h.z = h.z >= 0.f ? h.z : 0.5f * h.z;
    h.w = h.w >= 0.f ? h.w : 0.5f * h.w;
    return h;
}

__device__ __forceinline__ void mask_edge(unsigned tid, float* __restrict__ mvOut,
                                          const float* __restrict__ av,
                                          const float* __restrict__ tv,
                                          const float* __restrict__ sv,
                                          uint32_t ka1, uint32_t ka2,
                                          uint32_t kt1, uint32_t kt2,
                                          uint32_t ku1, uint32_t ku2) {
    const float* v; uint32_t k1, k2; unsigned e, off;
    if (tid < EADJ)              { v = av; k1 = ka1; k2 = ka2; e = tid;               off = 0; }
    else if (tid < EADJ + ETAG)  { v = tv; k1 = kt1; k2 = kt2; e = tid - EADJ;        off = EADJ; }
    else                         { v = sv; k1 = ku1; k2 = ku2; e = tid - EADJ - ETAG; off = EADJ + ETAG; }
    uint32_t bits = tf_bits(k1, k2, e);
    float u = __uint_as_float((bits >> 9) | 0x3f800000u) - 1.0f;
    float keep = floorf(u + 0.9f);
    mvOut[off + e] = (__ldg(v + e) * keep) * (float)(1.0 / 0.9);
}

// ---------------- kernels ----------------

// Blocks [0, MB_P1): layer-0 mask, tids [0, 2000128).
// Blocks [MB_P1, MB_P1+INITB): init lat/out/taglat + zero all accumulators.
__global__ void prep_kernel(const float4* __restrict__ u4,
                            const float4* __restrict__ i4,
                            const float4* __restrict__ t4,
                            float4* __restrict__ out,
                            uint32_t ka1, uint32_t ka2, uint32_t kt1, uint32_t kt2,
                            uint32_t ku1, uint32_t ku2,
                            const float* __restrict__ av,
                            const float* __restrict__ tv,
                            const float* __restrict__ sv) {
    if (blockIdx.x < MB_P1) {
        unsigned tid = blockIdx.x * TB + threadIdx.x;
        mask_edge(tid, g_mv[0], av, tv, sv, ka1, ka2, kt1, kt2, ku1, ku2);
        return;
    }
    unsigned idx = (blockIdx.x - MB_P1) * TB + threadIdx.x;   // < NADJ*R4
    float4 s = (idx < USER_N * R4) ? __ldg(u4 + idx) : __ldg(i4 + idx - USER_N * R4);
    g_lat[idx] = s;
    out[idx]   = s;
    if (idx < MTAG * R4)
        g_taglat[idx] = (idx < ITEM_N * R4) ? __ldg(i4 + idx) : __ldg(t4 + idx - ITEM_N * R4);
    const float4 z = make_float4(0.f, 0.f, 0.f, 0.f);
    g_tem[idx] = z;
    const unsigned NG = MTAG * R4, NS = USER_N * R4;
    for (unsigned k = idx; k < 2 * NG + NS; k += (unsigned)NADJ * R4) {
        if (k < NG)          g_tg[0][k] = z;
        else if (k < 2 * NG) g_tg[1][k - NG] = z;
        else                 g_soc[k - 2 * NG] = z;
    }
}

// Fused: blocks [0, maskBlocks) compute masks for tids [maskOff, maskOff+maskBlocks*TB)
// into g_mv[maskLayer]; remaining blocks run SPMM (adj / tag / soc sub-ranges) for
// spmmLayer with high-MLP batched loads.
__global__ void work_kernel(int maskBlocks, unsigned maskOff, int maskLayer,
                            int spmmLayer, int nA, int nT, int nS,
                            uint32_t ka1, uint32_t ka2, uint32_t kt1, uint32_t kt2,
                            uint32_t ku1, uint32_t ku2,
                            const float* __restrict__ av,
                            const float* __restrict__ tv,
                            const float* __restrict__ sv,
                            const int* __restrict__ ar, const int* __restrict__ ac,
                            const int* __restrict__ tr, const int* __restrict__ tc,
                            const int* __restrict__ sr, const int* __restrict__ sc) {
    (void)nS;
    if ((int)blockIdx.x < maskBlocks) {
        unsigned tid = maskOff + blockIdx.x * TB + threadIdx.x;
        mask_edge(tid, g_mv[maskLayer], av, tv, sv, ka1, ka2, kt1, kt2, ku1, ku2);
        return;
    }
    unsigned sbid = blockIdx.x - maskBlocks;
    const float* mvIn = g_mv[spmmLayer];
    const int *rows, *cols; const float* mv; float4* outb; int mode; unsigned wb, Eg;
    if ((int)sbid < nA) {
        rows = ar; cols = ac; mv = mvIn;                outb = g_tem;           mode = 0; wb = sbid;           Eg = EADJ;
    } else if ((int)sbid < nA + nT) {
        rows = tr; cols = tc; mv = mvIn + EADJ;         outb = g_tg[spmmLayer]; mode = 1; wb = sbid - nA;      Eg = ETAG;
    } else {
        rows = sr; cols = sc; mv = mvIn + EADJ + ETAG;  outb = g_soc;           mode = 2; wb = sbid - nA - nT; Eg = ESOC;
    }
    unsigned lane  = threadIdx.x & 31u;
    unsigned warp  = threadIdx.x >> 5;
    unsigned chunk = lane & 15u;
    unsigned e0    = wb * EPB + warp * 2u + (lane >> 4);

    // stage 1: all edge metadata (independent loads, broadcast within 16-lane group)
    float v[NE]; int rr[NE], cc[NE];
#pragma unroll
    for (int i = 0; i < NE; ++i) {
        unsigned e  = e0 + 16u * i;
        unsigned ec = e < Eg ? e : Eg - 1u;
        float vv = __ldg(mv + ec);
        v[i]  = (e < Eg) ? vv : 0.f;
        rr[i] = __ldg(rows + ec);
        cc[i] = __ldg(cols + ec);
    }
    // stage 2: all gathers in flight (unconditional: indices always valid)
    float4 xv[NE];
#pragma unroll
    for (int i = 0; i < NE; ++i) {
        const float4* x;
        if (mode == 1)
            x = (cc[i] < ITEM_N) ? (g_lat + (unsigned)(USER_N + cc[i]) * R4)
                                 : (g_taglat + (unsigned)cc[i] * R4);
        else
            x = g_lat + (unsigned)cc[i] * R4;
        xv[i] = __ldg(x + chunk);
    }
    // stage 3: predicated scatter-reduce
#pragma unroll
    for (int i = 0; i < NE; ++i) {
        if (v[i] != 0.f) {
            float4* dst = outb + (unsigned)rr[i] * R4 + chunk;
            asm volatile("red.global.add.v4.f32 [%0], {%1,%2,%3,%4};"
                         :: "l"(dst), "f"(v[i] * xv[i].x), "f"(v[i] * xv[i].y),
                            "f"(v[i] * xv[i].z), "f"(v[i] * xv[i].w)
                         : "memory");
        }
    }
}

// MID=true (layer 0): also write lat/taglat for next layer and zero tem/soc.
template <bool MID>
__global__ void combine_kernel(float4* __restrict__ out, int layer) {
    unsigned idx = blockIdx.x * TB + threadIdx.x;   // < NADJ*R4
    const float4* tg = g_tg[layer];
    const float4 z = make_float4(0.f, 0.f, 0.f, 0.f);
    float4 t = leaky4(g_tem[idx]);
    float4 o;
    if (idx < USER_N * R4) {
        float4 s = leaky4(g_soc[idx]);
        o = make_float4(t.x + s.x, t.y + s.y, t.z + s.z, t.w + s.w);
        if (MID) g_soc[idx] = z;
    } else {
        float4 gv = leaky4(tg[idx - USER_N * R4]);
        o = make_float4(t.x + gv.x, t.y + gv.y, t.z + gv.z, t.w + gv.w);
    }
    if (MID) { g_tem[idx] = z; g_lat[idx] = o; }
    float4 a = out[idx];
    a.x += o.x; a.y += o.y; a.z += o.z; a.w += o.w;
    out[idx] = a;
    if (MID && idx < MTAG * R4)
        g_taglat[idx] = leaky4(tg[idx]);
}

// ---------------- launch ----------------
extern "C" void kernel_launch(void* const* d_in, const int* in_sizes, int n_in,
                              void* d_out, int out_size) {
    const float4* uE = (const float4*)d_in[0];
    const float4* iE = (const float4*)d_in[1];
    const float4* tE = (const float4*)d_in[2];
    const int*   ar = (const int*)d_in[3];
    const int*   ac = (const int*)d_in[4];
    const float* av = (const float*)d_in[5];
    const int*   tr = (const int*)d_in[6];
    const int*   tc = (const int*)d_in[7];
    const float* tv = (const float*)d_in[8];
    const int*   sr = (const int*)d_in[9];
    const int*   sc = (const int*)d_in[10];
    const float* sv = (const float*)d_in[11];
    float4* out = (float4*)d_out;

    // jax.random.key(42) -> (0, 42); fold_in(key, j) = threefry2x32(key, (0, j))
    uint32_t fk[6][2];
    for (uint32_t j = 0; j < 6; ++j)
        h_threefry(0u, 42u, 0u, j, &fk[j][0], &fk[j][1]);

    // P1: mask0 tids [0, 2000128) || init + zero
    prep_kernel<<<MB_P1 + INITB, TB>>>(uE, iE, tE, out,
                                       fk[0][0], fk[0][1], fk[1][0], fk[1][1],
                                       fk[2][0], fk[2][1], av, tv, sv);
    // P2: mask0 tids [2000128, 4000000) || spmm0(adj)
    work_kernel<<<MB_P2 + A_BLK, TB>>>(MB_P2, (unsigned)MB_P1 * TB, 0,
                                       0, A_BLK, 0, 0,
                                       fk[0][0], fk[0][1], fk[1][0], fk[1][1],
                                       fk[2][0], fk[2][1],
                                       av, tv, sv, ar, ac, tr, tc, sr, sc);
    // P3: mask1 (all) || spmm0(tag + soc)
    work_kernel<<<MB_ALL + T_BLK + S_BLK, TB>>>(MB_ALL, 0u, 1,
                                                0, 0, T_BLK, S_BLK,
                                                fk[3][0], fk[3][1], fk[4][0], fk[4][1],
                                                fk[5][0], fk[5][1],
                                                av, tv, sv, ar, ac, tr, tc, sr, sc);
    // P4: combine0 (+ zero tem/soc for layer 1)
    combine_kernel<true><<<INITB, TB>>>(out, 0);
    // P5: spmm1 (all graphs, no mask work)
    work_kernel<<<A_BLK + T_BLK + S_BLK, TB>>>(0, 0u, 1,
                                               1, A_BLK, T_BLK, S_BLK,
                                               0u, 0u, 0u, 0u, 0u, 0u,
                                               av, tv, sv, ar, ac, tr, tc, sr, sc);
    // P6: combine1 (final)
    combine_kernel<false><<<INITB, TB>>>(out, 1);
}

// round 6
// speedup vs baseline: 1.4456x; 1.1702x over previous
#include <cuda_runtime.h>
#include <stdint.h>

// ---------------- problem constants ----------------
#define USER_N 100000
#define ITEM_N 50000
#define TAG_N  20000
#define NADJ   (USER_N + ITEM_N)   // 150000
#define MTAG   (ITEM_N + TAG_N)    // 70000
#define EADJ   2000000
#define ETAG   1000000
#define ESOC   1000000
#define ETOT   (EADJ + ETAG + ESOC)  // 4,000,000
#define R4     16                    // D=64 floats = 16 float4
#define NELEM  (NADJ * R4)           // 2,400,000 float4
#define TB     256

#define EPB    128                   // edges per spmm block
#define NE     (EPB / 16)            // 8 edges per thread-slot
#define A_BLK  (EADJ / EPB)                  // 15625 (exact)
#define T_BLK  ((ETAG + EPB - 1) / EPB)      // 7813
#define S_BLK  ((ESOC + EPB - 1) / EPB)      // 7813

// mask halves: [0, 2000128) and [2000128, 4000000)
#define MB_H1  7813                  // covers all adj edges (+128 tag)
#define MB_H2  (ETOT / TB - MB_H1)   // 7812
#define INITB  (NELEM / TB)          // 9375
#define COMBB  ((NELEM + 2 * TB - 1) / (2 * TB))   // 4688 (2 float4/thread)

// ---------------- device scratch ----------------
__device__ float4 g_lat[NELEM];
__device__ float4 g_taglat[MTAG * R4];
__device__ float4 g_tem[NELEM];
__device__ float4 g_tg[2][MTAG * R4];     // double-buffered (no zero-race)
__device__ float4 g_soc[USER_N * R4];
__device__ float  g_mv[2][ETOT];          // masked edge values per layer

// ---------------- threefry-2x32-20 (JAX partitionable, bit-exact) ----------------
__device__ __forceinline__ uint32_t d_rotl(uint32_t v, int r) {
    return __funnelshift_l(v, v, r);
}
__device__ __forceinline__ uint32_t tf_bits(uint32_t K1, uint32_t K2, uint32_t ctr) {
    uint32_t ks2 = K1 ^ K2 ^ 0x1BD11BDAu;
    uint32_t x0 = K1;
    uint32_t x1 = ctr + K2;
#define TF_R4(a,b,c,d)                                        \
    x0 += x1; x1 = d_rotl(x1,a); x1 ^= x0;                    \
    x0 += x1; x1 = d_rotl(x1,b); x1 ^= x0;                    \
    x0 += x1; x1 = d_rotl(x1,c); x1 ^= x0;                    \
    x0 += x1; x1 = d_rotl(x1,d); x1 ^= x0;
    TF_R4(13,15,26,6)   x0 += K2;  x1 += ks2 + 1u;
    TF_R4(17,29,16,24)  x0 += ks2; x1 += K1  + 2u;
    TF_R4(13,15,26,6)   x0 += K1;  x1 += K2  + 3u;
    TF_R4(17,29,16,24)  x0 += K2;  x1 += ks2 + 4u;
    TF_R4(13,15,26,6)   x0 += ks2; x1 += K1  + 5u;
#undef TF_R4
    return x0 ^ x1;
}

static inline uint32_t h_rotl(uint32_t v, int r) { return (v << r) | (v >> (32 - r)); }
static void h_threefry(uint32_t K1, uint32_t K2, uint32_t x0, uint32_t x1,
                       uint32_t* o0, uint32_t* o1) {
    uint32_t ks[3] = {K1, K2, K1 ^ K2 ^ 0x1BD11BDAu};
    static const int rots[2][4] = {{13,15,26,6},{17,29,16,24}};
    x0 += ks[0]; x1 += ks[1];
    for (int g = 0; g < 5; ++g) {
        const int* rr = rots[g & 1];
        for (int j = 0; j < 4; ++j) { x0 += x1; x1 = h_rotl(x1, rr[j]); x1 ^= x0; }
        x0 += ks[(g + 1) % 3];
        x1 += ks[(g + 2) % 3] + (uint32_t)(g + 1);
    }
    *o0 = x0; *o1 = x1;
}

// ---------------- helpers ----------------
__device__ __forceinline__ float4 leaky4(float4 h) {
    h.x = h.x >= 0.f ? h.x : 0.5f * h.x;
    h.y = h.y >= 0.f ? h.y : 0.5f * h.y;
    h.z = h.z >= 0.f ? h.z : 0.5f * h.z;
    h.w = h.w >= 0.f ? h.w : 0.5f * h.w;
    return h;
}
__device__ __forceinline__ float4 add4(float4 a, float4 b) {
    return make_float4(a.x + b.x, a.y + b.y, a.z + b.z, a.w + b.w);
}

__device__ __forceinline__ void mask_edge(unsigned tid, float* __restrict__ mvOut,
                                          const float* __restrict__ av,
                                          const float* __restrict__ tv,
                                          const float* __restrict__ sv,
                                          uint32_t ka1, uint32_t ka2,
                                          uint32_t kt1, uint32_t kt2,
                                          uint32_t ku1, uint32_t ku2) {
    const float* v; uint32_t k1, k2; unsigned e, off;
    if (tid < EADJ)              { v = av; k1 = ka1; k2 = ka2; e = tid;               off = 0; }
    else if (tid < EADJ + ETAG)  { v = tv; k1 = kt1; k2 = kt2; e = tid - EADJ;        off = EADJ; }
    else                         { v = sv; k1 = ku1; k2 = ku2; e = tid - EADJ - ETAG; off = EADJ + ETAG; }
    uint32_t bits = tf_bits(k1, k2, e);
    float u = __uint_as_float((bits >> 9) | 0x3f800000u) - 1.0f;
    float keep = floorf(u + 0.9f);
    mvOut[off + e] = (__ldg(v + e) * keep) * (float)(1.0 / 0.9);
}

// ---------------- kernels ----------------

// Blocks [0, MB_H1): layer-0 mask, tids [0, 2000128).
// Blocks [MB_H1, MB_H1+INITB): init lat/out(=lat0)/taglat + zero accumulators.
__global__ void prep_kernel(const float4* __restrict__ u4,
                            const float4* __restrict__ i4,
                            const float4* __restrict__ t4,
                            float4* __restrict__ out,
                            uint32_t ka1, uint32_t ka2, uint32_t kt1, uint32_t kt2,
                            uint32_t ku1, uint32_t ku2,
                            const float* __restrict__ av,
                            const float* __restrict__ tv,
                            const float* __restrict__ sv) {
    if (blockIdx.x < MB_H1) {
        unsigned tid = blockIdx.x * TB + threadIdx.x;
        mask_edge(tid, g_mv[0], av, tv, sv, ka1, ka2, kt1, kt2, ku1, ku2);
        return;
    }
    unsigned idx = (blockIdx.x - MB_H1) * TB + threadIdx.x;   // < NELEM
    float4 s = (idx < USER_N * R4) ? __ldg(u4 + idx) : __ldg(i4 + idx - USER_N * R4);
    float4 tl = make_float4(0.f, 0.f, 0.f, 0.f);
    if (idx < MTAG * R4)
        tl = (idx < ITEM_N * R4) ? __ldg(i4 + idx) : __ldg(t4 + idx - ITEM_N * R4);
    g_lat[idx] = s;
    out[idx]   = s;
    if (idx < MTAG * R4) g_taglat[idx] = tl;
    const float4 z = make_float4(0.f, 0.f, 0.f, 0.f);
    g_tem[idx] = z;
    const unsigned NG = MTAG * R4, NS = USER_N * R4;
    for (unsigned k = idx; k < 2 * NG + NS; k += (unsigned)NELEM) {
        if (k < NG)          g_tg[0][k] = z;
        else if (k < 2 * NG) g_tg[1][k - NG] = z;
        else                 g_soc[k - 2 * NG] = z;
    }
}

// Fused: blocks [0, maskBlocks) compute masks for tids [maskOff, ...) into
// g_mv[maskLayer]; remaining blocks run SPMM sub-ranges with batched MLP loads.
__global__ void work_kernel(int maskBlocks, unsigned maskOff, int maskLayer,
                            int spmmLayer, int nA, int nT,
                            uint32_t ka1, uint32_t ka2, uint32_t kt1, uint32_t kt2,
                            uint32_t ku1, uint32_t ku2,
                            const float* __restrict__ av,
                            const float* __restrict__ tv,
                            const float* __restrict__ sv,
                            const int* __restrict__ ar, const int* __restrict__ ac,
                            const int* __restrict__ tr, const int* __restrict__ tc,
                            const int* __restrict__ sr, const int* __restrict__ sc) {
    if ((int)blockIdx.x < maskBlocks) {
        unsigned tid = maskOff + blockIdx.x * TB + threadIdx.x;
        mask_edge(tid, g_mv[maskLayer], av, tv, sv, ka1, ka2, kt1, kt2, ku1, ku2);
        return;
    }
    unsigned sbid = blockIdx.x - maskBlocks;
    const float* mvIn = g_mv[spmmLayer];
    const int *rows, *cols; const float* mv; float4* outb; int mode; unsigned wb, Eg;
    if ((int)sbid < nA) {
        rows = ar; cols = ac; mv = mvIn;                outb = g_tem;           mode = 0; wb = sbid;           Eg = EADJ;
    } else if ((int)sbid < nA + nT) {
        rows = tr; cols = tc; mv = mvIn + EADJ;         outb = g_tg[spmmLayer]; mode = 1; wb = sbid - nA;      Eg = ETAG;
    } else {
        rows = sr; cols = sc; mv = mvIn + EADJ + ETAG;  outb = g_soc;           mode = 2; wb = sbid - nA - nT; Eg = ESOC;
    }
    unsigned lane  = threadIdx.x & 31u;
    unsigned warp  = threadIdx.x >> 5;
    unsigned chunk = lane & 15u;
    unsigned e0    = wb * EPB + warp * 2u + (lane >> 4);

    float v[NE]; int rr[NE], cc[NE];
#pragma unroll
    for (int i = 0; i < NE; ++i) {
        unsigned e  = e0 + 16u * i;
        unsigned ec = e < Eg ? e : Eg - 1u;
        float vv = __ldg(mv + ec);
        v[i]  = (e < Eg) ? vv : 0.f;
        rr[i] = __ldg(rows + ec);
        cc[i] = __ldg(cols + ec);
    }
    float4 xv[NE];
#pragma unroll
    for (int i = 0; i < NE; ++i) {
        const float4* x;
        if (mode == 1)
            x = (cc[i] < ITEM_N) ? (g_lat + (unsigned)(USER_N + cc[i]) * R4)
                                 : (g_taglat + (unsigned)cc[i] * R4);
        else
            x = g_lat + (unsigned)cc[i] * R4;
        xv[i] = __ldg(x + chunk);
    }
#pragma unroll
    for (int i = 0; i < NE; ++i) {
        if (v[i] != 0.f) {
            float4* dst = outb + (unsigned)rr[i] * R4 + chunk;
            asm volatile("red.global.add.v4.f32 [%0], {%1,%2,%3,%4};"
                         :: "l"(dst), "f"(v[i] * xv[i].x), "f"(v[i] * xv[i].y),
                            "f"(v[i] * xv[i].z), "f"(v[i] * xv[i].w)
                         : "memory");
        }
    }
}

// Fused: blocks [0, MB_H2) = mask1 second half; rest = combine-mid.
// Combine-mid: lat = leaky(tem) + leaky(soc|tg0); taglat = leaky(tg0);
// zero tem/soc. Does NOT touch out. ALL loads issued before ANY store
// (loads can't be reordered below unrelated-global stores due to possible
// aliasing with the out parameter elsewhere — keep them first in program order).
__global__ void mid_kernel(uint32_t ka1, uint32_t ka2, uint32_t kt1, uint32_t kt2,
                           uint32_t ku1, uint32_t ku2,
                           const float* __restrict__ av,
                           const float* __restrict__ tv,
                           const float* __restrict__ sv) {
    if (blockIdx.x < MB_H2) {
        unsigned tid = (unsigned)MB_H1 * TB + blockIdx.x * TB + threadIdx.x;
        mask_edge(tid, g_mv[1], av, tv, sv, ka1, ka2, kt1, kt2, ku1, ku2);
        return;
    }
    const float4 z = make_float4(0.f, 0.f, 0.f, 0.f);
    unsigned base = (blockIdx.x - MB_H2) * (2u * TB) + threadIdx.x;
    unsigned ia = base, ib = base + TB;
    bool va = ia < NELEM, vb = ib < NELEM;
    unsigned a = va ? ia : 0u, b = vb ? ib : 0u;
    bool ua = a < USER_N * R4, ub = b < USER_N * R4;
    bool ma = a < MTAG * R4,   mbb = b < MTAG * R4;
    // ---- loads ----
    float4 ta = g_tem[a];
    float4 tb4 = g_tem[b];
    float4 sa = ua ? g_soc[a] : g_tg[0][a - USER_N * R4];
    float4 sb = ub ? g_soc[b] : g_tg[0][b - USER_N * R4];
    float4 ga = ma  ? g_tg[0][a] : z;
    float4 gb = mbb ? g_tg[0][b] : z;
    // ---- compute ----
    float4 oa = add4(leaky4(ta),  leaky4(sa));
    float4 ob = add4(leaky4(tb4), leaky4(sb));
    // ---- stores ----
    if (va) {
        g_lat[a] = oa; g_tem[a] = z;
        if (ua) g_soc[a] = z;
        if (ma) g_taglat[a] = leaky4(ga);
    }
    if (vb) {
        g_lat[b] = ob; g_tem[b] = z;
        if (ub) g_soc[b] = z;
        if (mbb) g_taglat[b] = leaky4(gb);
    }
}

// Final: out = out(lat0) + g_lat(lat1) + (leaky(tem)+leaky(soc|tg1)).
__global__ void fin_kernel(float4* __restrict__ out) {
    unsigned base = blockIdx.x * (2u * TB) + threadIdx.x;
    unsigned ia = base, ib = base + TB;
    bool va = ia < NELEM, vb = ib < NELEM;
    unsigned a = va ? ia : 0u, b = vb ? ib : 0u;
    bool ua = a < USER_N * R4, ub = b < USER_N * R4;
    // ---- loads ----
    float4 ta = g_tem[a];
    float4 tb4 = g_tem[b];
    float4 sa = ua ? g_soc[a] : g_tg[1][a - USER_N * R4];
    float4 sb = ub ? g_soc[b] : g_tg[1][b - USER_N * R4];
    float4 la = g_lat[a];
    float4 lb = g_lat[b];
    float4 o0a = out[a];
    float4 o0b = out[b];
    // ---- compute + stores ----
    float4 l2a = add4(leaky4(ta),  leaky4(sa));
    float4 l2b = add4(leaky4(tb4), leaky4(sb));
    if (va) out[a] = add4(add4(o0a, la), l2a);
    if (vb) out[b] = add4(add4(o0b, lb), l2b);
}

// ---------------- launch ----------------
extern "C" void kernel_launch(void* const* d_in, const int* in_sizes, int n_in,
                              void* d_out, int out_size) {
    const float4* uE = (const float4*)d_in[0];
    const float4* iE = (const float4*)d_in[1];
    const float4* tE = (const float4*)d_in[2];
    const int*   ar = (const int*)d_in[3];
    const int*   ac = (const int*)d_in[4];
    const float* av = (const float*)d_in[5];
    const int*   tr = (const int*)d_in[6];
    const int*   tc = (const int*)d_in[7];
    const float* tv = (const float*)d_in[8];
    const int*   sr = (const int*)d_in[9];
    const int*   sc = (const int*)d_in[10];
    const float* sv = (const float*)d_in[11];
    float4* out = (float4*)d_out;

    // jax.random.key(42) -> (0, 42); fold_in(key, j) = threefry2x32(key, (0, j))
    uint32_t fk[6][2];
    for (uint32_t j = 0; j < 6; ++j)
        h_threefry(0u, 42u, 0u, j, &fk[j][0], &fk[j][1]);

    // P1: mask0 [0, 2000128) || init + zero (out = lat0)
    prep_kernel<<<MB_H1 + INITB, TB>>>(uE, iE, tE, out,
                                       fk[0][0], fk[0][1], fk[1][0], fk[1][1],
                                       fk[2][0], fk[2][1], av, tv, sv);
    // P2: mask0 [2000128, 4M) || spmm0(adj)
    work_kernel<<<MB_H2 + A_BLK, TB>>>(MB_H2, (unsigned)MB_H1 * TB, 0,
                                       0, A_BLK, 0,
                                       fk[0][0], fk[0][1], fk[1][0], fk[1][1],
                                       fk[2][0], fk[2][1],
                                       av, tv, sv, ar, ac, tr, tc, sr, sc);
    // P3: mask1 [0, 2000128) || spmm0(tag + soc)
    work_kernel<<<MB_H1 + T_BLK + S_BLK, TB>>>(MB_H1, 0u, 1,
                                               0, 0, T_BLK,
                                               fk[3][0], fk[3][1], fk[4][0], fk[4][1],
                                               fk[5][0], fk[5][1],
                                               av, tv, sv, ar, ac, tr, tc, sr, sc);
    // P4: mask1 [2000128, 4M) || combine-mid
    mid_kernel<<<MB_H2 + COMBB, TB>>>(fk[3][0], fk[3][1], fk[4][0], fk[4][1],
                                      fk[5][0], fk[5][1], av, tv, sv);
    // P5: spmm1 (all graphs)
    work_kernel<<<A_BLK + T_BLK + S_BLK, TB>>>(0, 0u, 1,
                                               1, A_BLK, T_BLK,
                                               0u, 0u, 0u, 0u, 0u, 0u,
                                               av, tv, sv, ar, ac, tr, tc, sr, sc);
    // P6: combine-final
    fin_kernel<<<COMBB, TB>>>(out);
}

// round 8
// speedup vs baseline: 1.8811x; 1.3013x over previous
#include <cuda_runtime.h>
#include <stdint.h>

// ---------------- problem constants ----------------
#define USER_N 100000
#define ITEM_N 50000
#define TAG_N  20000
#define NADJ   (USER_N + ITEM_N)   // 150000
#define MTAG   (ITEM_N + TAG_N)    // 70000
#define EADJ   2000000
#define ETAG   1000000
#define ESOC   1000000
#define R4     16                    // D=64 floats = 16 float4
#define NELEM  (NADJ * R4)           // 2,400,000 float4
#define UELEM  (USER_N * R4)         // 1,600,000
#define IELEM  (ITEM_N * R4)         //   800,000
#define GELEM  (MTAG * R4)           // 1,120,000
#define TELEM  (TAG_N * R4)          //   320,000
#define TB     256

#define EPB    128                   // edges per block
#define EPW    16                    // edges per warp
#define NE     8                     // edges per 16-lane slot
#define A_BLK  (EADJ / EPB)                  // 15625 (exact)
#define T_BLK  ((ETAG + EPB - 1) / EPB)      // 7813
#define S_BLK  ((ESOC + EPB - 1) / EPB)      // 7813
#define SPMMB  (A_BLK + T_BLK + S_BLK)       // 31251
#define COMBB  ((NELEM + 2 * TB - 1) / (2 * TB))   // 4688

// ---------------- device scratch (zero-initialized at module load; every call
// re-zeroes what it dirties -> accumulators are always zero on entry) ---------
__device__ float4 g_lat[NELEM];           // lat after layer 0 (written by mid)
__device__ float4 g_taglat[GELEM];        // taglat after layer 0 (tag part used)
__device__ float4 g_tem[NELEM];           // adj accumulator
__device__ float4 g_tg[2][GELEM];         // tag accumulator per layer
__device__ float4 g_soc[UELEM];           // soc accumulator

// ---------------- threefry-2x32-20 (JAX partitionable, bit-exact) ----------------
__device__ __forceinline__ uint32_t d_rotl(uint32_t v, int r) {
    return __funnelshift_l(v, v, r);
}
__device__ __forceinline__ uint32_t tf_bits(uint32_t K1, uint32_t K2, uint32_t ctr) {
    uint32_t ks2 = K1 ^ K2 ^ 0x1BD11BDAu;
    uint32_t x0 = K1;
    uint32_t x1 = ctr + K2;
#define TF_R4(a,b,c,d)                                        \
    x0 += x1; x1 = d_rotl(x1,a); x1 ^= x0;                    \
    x0 += x1; x1 = d_rotl(x1,b); x1 ^= x0;                    \
    x0 += x1; x1 = d_rotl(x1,c); x1 ^= x0;                    \
    x0 += x1; x1 = d_rotl(x1,d); x1 ^= x0;
    TF_R4(13,15,26,6)   x0 += K2;  x1 += ks2 + 1u;
    TF_R4(17,29,16,24)  x0 += ks2; x1 += K1  + 2u;
    TF_R4(13,15,26,6)   x0 += K1;  x1 += K2  + 3u;
    TF_R4(17,29,16,24)  x0 += K2;  x1 += ks2 + 4u;
    TF_R4(13,15,26,6)   x0 += ks2; x1 += K1  + 5u;
#undef TF_R4
    return x0 ^ x1;
}

static inline uint32_t h_rotl(uint32_t v, int r) { return (v << r) | (v >> (32 - r)); }
static void h_threefry(uint32_t K1, uint32_t K2, uint32_t x0, uint32_t x1,
                       uint32_t* o0, uint32_t* o1) {
    uint32_t ks[3] = {K1, K2, K1 ^ K2 ^ 0x1BD11BDAu};
    static const int rots[2][4] = {{13,15,26,6},{17,29,16,24}};
    x0 += ks[0]; x1 += ks[1];
    for (int g = 0; g < 5; ++g) {
        const int* rr = rots[g & 1];
        for (int j = 0; j < 4; ++j) { x0 += x1; x1 = h_rotl(x1, rr[j]); x1 ^= x0; }
        x0 += ks[(g + 1) % 3];
        x1 += ks[(g + 2) % 3] + (uint32_t)(g + 1);
    }
    *o0 = x0; *o1 = x1;
}

// ---------------- helpers ----------------
__device__ __forceinline__ float4 leaky4(float4 h) {
    h.x = h.x >= 0.f ? h.x : 0.5f * h.x;
    h.y = h.y >= 0.f ? h.y : 0.5f * h.y;
    h.z = h.z >= 0.f ? h.z : 0.5f * h.z;
    h.w = h.w >= 0.f ? h.w : 0.5f * h.w;
    return h;
}
__device__ __forceinline__ float4 add4(float4 a, float4 b) {
    return make_float4(a.x + b.x, a.y + b.y, a.z + b.z, a.w + b.w);
}

// ---------------- fused mask+SPMM ----------------
// One warp = 16 edges. Lanes 0..15 each compute one edge's threefry mask and
// metadata (coalesced); results are distributed to the two 16-lane slots via
// shuffles. Each slot then does 8 MLP-batched gathers + predicated red.v4.
// LAYER 0 gathers straight from the input embeddings (lat0 = concat(u,i),
// taglat0 = concat(i,t)); LAYER 1 gathers from g_lat / g_taglat.
template <int LAYER>
__global__ void spmm_kernel(const float4* __restrict__ u4,
                            const float4* __restrict__ i4,
                            const float4* __restrict__ t4,
                            uint32_t ka1, uint32_t ka2, uint32_t kt1, uint32_t kt2,
                            uint32_t ku1, uint32_t ku2,
                            const float* __restrict__ av,
                            const float* __restrict__ tv,
                            const float* __restrict__ sv,
                            const int* __restrict__ ar, const int* __restrict__ ac,
                            const int* __restrict__ tr, const int* __restrict__ tc,
                            const int* __restrict__ sr, const int* __restrict__ sc) {
    unsigned sbid = blockIdx.x;
    const int *rows, *cols; const float* vals; float4* outb;
    int mode; unsigned wb, Eg; uint32_t k1, k2;
    if (sbid < A_BLK) {
        rows = ar; cols = ac; vals = av; outb = g_tem;       mode = 0; wb = sbid;                 Eg = EADJ; k1 = ka1; k2 = ka2;
    } else if (sbid < A_BLK + T_BLK) {
        rows = tr; cols = tc; vals = tv; outb = g_tg[LAYER]; mode = 1; wb = sbid - A_BLK;         Eg = ETAG; k1 = kt1; k2 = kt2;
    } else {
        rows = sr; cols = sc; vals = sv; outb = g_soc;       mode = 2; wb = sbid - A_BLK - T_BLK; Eg = ESOC; k1 = ku1; k2 = ku2;
    }
    unsigned lane  = threadIdx.x & 31u;
    unsigned warp  = threadIdx.x >> 5;
    unsigned chunk = lane & 15u;
    unsigned slot  = lane >> 4;
    unsigned ebase = wb * EPB + warp * EPW;
    unsigned el    = ebase + (lane & 15u);       // edge this lane masks
    unsigned elc   = el < Eg ? el : Eg - 1u;

    // coalesced metadata loads (lanes 16..31 duplicate 0..15 -> broadcast)
    float vraw = __ldg(vals + elc);
    int   rl   = __ldg(rows + elc);
    int   cl   = __ldg(cols + elc);
    // inline dropout mask (independent of gather path; fills latency bubbles)
    uint32_t bits = tf_bits(k1, k2, elc);
    float u    = __uint_as_float((bits >> 9) | 0x3f800000u) - 1.0f;
    float mval = (el < Eg) ? (vraw * floorf(u + 0.9f)) * (float)(1.0 / 0.9) : 0.f;

    // distribute: slot s, iter i -> warp-local edge j = 2*i + s
    float v[NE]; int rr[NE], cc[NE];
#pragma unroll
    for (int i = 0; i < NE; ++i) {
        int j = 2 * i + (int)slot;
        v[i]  = __shfl_sync(0xffffffffu, mval, j);
        rr[i] = __shfl_sync(0xffffffffu, rl,   j);
        cc[i] = __shfl_sync(0xffffffffu, cl,   j);
    }
    // MLP-batched gathers (unconditional: indices always valid)
    float4 xv[NE];
#pragma unroll
    for (int i = 0; i < NE; ++i) {
        int c = cc[i];
        const float4* x;
        if (LAYER == 0) {
            if (mode == 1)
                x = (c < ITEM_N) ? (i4 + (unsigned)c * R4)
                                 : (t4 + (unsigned)(c - ITEM_N) * R4);
            else
                x = (c < USER_N) ? (u4 + (unsigned)c * R4)
                                 : (i4 + (unsigned)(c - USER_N) * R4);
        } else {
            if (mode == 1)
                x = (c < ITEM_N) ? (g_lat + (unsigned)(USER_N + c) * R4)
                                 : (g_taglat + (unsigned)c * R4);
            else
                x = g_lat + (unsigned)c * R4;
        }
        xv[i] = __ldg(x + chunk);
    }
    // predicated scatter-reduce
#pragma unroll
    for (int i = 0; i < NE; ++i) {
        if (v[i] != 0.f) {
            float4* dst = outb + (unsigned)rr[i] * R4 + chunk;
            asm volatile("red.global.add.v4.f32 [%0], {%1,%2,%3,%4};"
                         :: "l"(dst), "f"(v[i] * xv[i].x), "f"(v[i] * xv[i].y),
                            "f"(v[i] * xv[i].z), "f"(v[i] * xv[i].w)
                         : "memory");
        }
    }
}

// combine-mid: lat = leaky(tem) + leaky(soc | tg0); taglat(tag part) = leaky(tg0);
// zero tem + soc (same-thread-after-read). tg[0] is zeroed later by fin.
// 2 float4 per thread, ALL loads before ANY store.
__global__ void mid_kernel() {
    const float4 z = make_float4(0.f, 0.f, 0.f, 0.f);
    unsigned base = blockIdx.x * (2u * TB) + threadIdx.x;
    unsigned ia = base, ib = base + TB;
    bool va = ia < NELEM, vb = ib < NELEM;
    unsigned a = va ? ia : 0u, b = vb ? ib : 0u;
    bool ua = a < UELEM, ub = b < UELEM;
    bool ga = (a >= IELEM) & (a < GELEM);      // taglat tag-part range
    bool gb = (b >= IELEM) & (b < GELEM);
    // ---- loads ----
    float4 ta  = g_tem[a];
    float4 tb4 = g_tem[b];
    float4 sa  = ua ? g_soc[a] : g_tg[0][a - UELEM];
    float4 sb  = ub ? g_soc[b] : g_tg[0][b - UELEM];
    float4 g0a = ga ? g_tg[0][a] : z;
    float4 g0b = gb ? g_tg[0][b] : z;
    // ---- compute ----
    float4 oa = add4(leaky4(ta),  leaky4(sa));
    float4 ob = add4(leaky4(tb4), leaky4(sb));
    // ---- stores ----
    if (va) {
        g_lat[a] = oa; g_tem[a] = z;
        if (ua) g_soc[a] = z;
        if (ga) g_taglat[a] = leaky4(g0a);
    }
    if (vb) {
        g_lat[b] = ob; g_tem[b] = z;
        if (ub) g_soc[b] = z;
        if (gb) g_taglat[b] = leaky4(g0b);
    }
}

// combine-final: out = (u|i) + g_lat + leaky(tem) + leaky(soc | tg1).
// Re-zeroes tem, soc, tg[1] item-part (same-thread-after-read) and, via the
// strided tail loop, tg[0] entirely + tg[1] tag tail (read by no one here).
__global__ void fin_kernel(float4* __restrict__ out,
                           const float4* __restrict__ u4,
                           const float4* __restrict__ i4) {
    const float4 z = make_float4(0.f, 0.f, 0.f, 0.f);
    unsigned base = blockIdx.x * (2u * TB) + threadIdx.x;
    unsigned ia = base, ib = base + TB;
    bool va = ia < NELEM, vb = ib < NELEM;
    unsigned a = va ? ia : 0u, b = vb ? ib : 0u;
    bool ua = a < UELEM, ub = b < UELEM;
    // ---- loads ----
    float4 ta  = g_tem[a];
    float4 tb4 = g_tem[b];
    float4 sa  = ua ? g_soc[a] : g_tg[1][a - UELEM];
    float4 sb  = ub ? g_soc[b] : g_tg[1][b - UELEM];
    float4 la  = g_lat[a];
    float4 lb  = g_lat[b];
    float4 ea  = ua ? __ldg(u4 + a) : __ldg(i4 + a - UELEM);
    float4 eb  = ub ? __ldg(u4 + b) : __ldg(i4 + b - UELEM);
    // ---- compute + stores ----
    float4 l2a = add4(leaky4(ta),  leaky4(sa));
    float4 l2b = add4(leaky4(tb4), leaky4(sb));
    if (va) {
        out[a] = add4(add4(ea, la), l2a);
        g_tem[a] = z;
        if (ua) g_soc[a] = z; else g_tg[1][a - UELEM] = z;
    }
    if (vb) {
        out[b] = add4(add4(eb, lb), l2b);
        g_tem[b] = z;
        if (ub) g_soc[b] = z; else g_tg[1][b - UELEM] = z;
    }
    // strided zero of buffers nobody reads in this kernel:
    // [0, GELEM) -> g_tg[0];  [GELEM, GELEM+TELEM) -> g_tg[1] tag tail
    const unsigned NTHR = (unsigned)COMBB * TB;        // 1,200,128
    unsigned gt = blockIdx.x * TB + threadIdx.x;
    for (unsigned k = gt; k < GELEM + TELEM; k += NTHR) {
        if (k < GELEM) g_tg[0][k] = z;
        else           g_tg[1][IELEM + (k - GELEM)] = z;
    }
}

// ---------------- launch ----------------
extern "C" void kernel_launch(void* const* d_in, const int* in_sizes, int n_in,
                              void* d_out, int out_size) {
    const float4* uE = (const float4*)d_in[0];
    const float4* iE = (const float4*)d_in[1];
    const float4* tE = (const float4*)d_in[2];
    const int*   ar = (const int*)d_in[3];
    const int*   ac = (const int*)d_in[4];
    const float* av = (const float*)d_in[5];
    const int*   tr = (const int*)d_in[6];
    const int*   tc = (const int*)d_in[7];
    const float* tv = (const float*)d_in[8];
    const int*   sr = (const int*)d_in[9];
    const int*   sc = (const int*)d_in[10];
    const float* sv = (const float*)d_in[11];
    float4* out = (float4*)d_out;

    // jax.random.key(42) -> (0, 42); fold_in(key, j) = threefry2x32(key, (0, j))
    uint32_t fk[6][2];
    for (uint32_t j = 0; j < 6; ++j)
        h_threefry(0u, 42u, 0u, j, &fk[j][0], &fk[j][1]);

    // layer 0: fused mask+spmm straight from the inputs
    spmm_kernel<0><<<SPMMB, TB>>>(uE, iE, tE,
                                  fk[0][0], fk[0][1], fk[1][0], fk[1][1],
                                  fk[2][0], fk[2][1],
                                  av, tv, sv, ar, ac, tr, tc, sr, sc);
    // combine-mid (writes lat/taglat, zeroes tem/soc)
    mid_kernel<<<COMBB, TB>>>();
    // layer 1: fused mask+spmm from g_lat / g_taglat
    spmm_kernel<1><<<SPMMB, TB>>>(uE, iE, tE,
                                  fk[3][0], fk[3][1], fk[4][0], fk[4][1],
                                  fk[5][0], fk[5][1],
                                  av, tv, sv, ar, ac, tr, tc, sr, sc);
    // combine-final (writes out, restores zero-state for next call)
    fin_kernel<<<COMBB, TB>>>(out, uE, iE);
}

// round 10
// speedup vs baseline: 2.0186x; 1.0731x over previous
#include <cuda_runtime.h>
#include <stdint.h>

// ---------------- problem constants ----------------
#define USER_N 100000
#define ITEM_N 50000
#define TAG_N  20000
#define NADJ   (USER_N + ITEM_N)   // 150000
#define MTAG   (ITEM_N + TAG_N)    // 70000
#define EADJ   2000000
#define ETAG   1000000
#define ESOC   1000000
#define ETOT   4000000
#define R4     16                    // D=64 floats = 16 float4
#define NELEM  (NADJ * R4)           // 2,400,000 float4
#define UELEM  (USER_N * R4)
#define IELEM  (ITEM_N * R4)
#define GELEM  (MTAG * R4)
#define TELEM  (TAG_N * R4)
#define TB     256

#define EPB    128                   // edges per spmm block
#define NE     8                     // consecutive edges per 16-lane slot
// sorted layout: adj [0, 2M), tag [2M, 3,000,064), soc [3,000,064, 4,000,128)
#define TAG_BASE  2000000
#define SOC_BASE  3000064            // 2M + 1,000,064 (tag padded to 128-mult)
#define SORT_N    4000128
#define A_SBLK (TAG_BASE / EPB)              // 15625
#define T_SBLK ((SOC_BASE - TAG_BASE) / EPB) // 7813
#define S_SBLK ((SORT_N - SOC_BASE) / EPB)   // 7813
#define SPMMB  (SORT_N / EPB)                // 31251
#define COMBB  ((NELEM + 2 * TB - 1) / (2 * TB))   // 4688

// bins: adj rows [0,150K) | tag rows [150K,220K) | soc rows [220K,320K)
#define NBINS  (NADJ + MTAG + USER_N)        // 320000
#define SOC_BIN0 (NADJ + MTAG)               // 220000
#define SCANB  313
#define NBINP  (SCANB * 1024)                // 320512 (padded)
#define EB     (ETOT / TB)                   // 15625 blocks for edge-parallel kernels

// ---------------- device scratch (zero-init at load; zero-on-exit invariant) ----
__device__ float4 g_lat[NELEM];
__device__ float4 g_taglat[GELEM];
__device__ float4 g_tem[NELEM];
__device__ float4 g_tg[2][GELEM];
__device__ float4 g_soc[UELEM];
__device__ uint4  g_bins4[NBINP / 4];        // histogram (zeroed by scatter each call)
__device__ uint4  g_binScan4[NBINP / 4];     // fully rewritten each call
__device__ uint32_t g_blkSum[SCANB];
__device__ uint32_t g_blkOff[SCANB];
__device__ uint4  g_sorted[SORT_N];          // (row, col, val_bits, local_idx); pads stay 0

// ---------------- threefry-2x32-20 (JAX partitionable, bit-exact) ----------------
__device__ __forceinline__ uint32_t d_rotl(uint32_t v, int r) {
    return __funnelshift_l(v, v, r);
}
__device__ __forceinline__ uint32_t tf_bits(uint32_t K1, uint32_t K2, uint32_t ctr) {
    uint32_t ks2 = K1 ^ K2 ^ 0x1BD11BDAu;
    uint32_t x0 = K1;
    uint32_t x1 = ctr + K2;
#define TF_R4(a,b,c,d)                                        \
    x0 += x1; x1 = d_rotl(x1,a); x1 ^= x0;                    \
    x0 += x1; x1 = d_rotl(x1,b); x1 ^= x0;                    \
    x0 += x1; x1 = d_rotl(x1,c); x1 ^= x0;                    \
    x0 += x1; x1 = d_rotl(x1,d); x1 ^= x0;
    TF_R4(13,15,26,6)   x0 += K2;  x1 += ks2 + 1u;
    TF_R4(17,29,16,24)  x0 += ks2; x1 += K1  + 2u;
    TF_R4(13,15,26,6)   x0 += K1;  x1 += K2  + 3u;
    TF_R4(17,29,16,24)  x0 += K2;  x1 += ks2 + 4u;
    TF_R4(13,15,26,6)   x0 += ks2; x1 += K1  + 5u;
#undef TF_R4
    return x0 ^ x1;
}

static inline uint32_t h_rotl(uint32_t v, int r) { return (v << r) | (v >> (32 - r)); }
static void h_threefry(uint32_t K1, uint32_t K2, uint32_t x0, uint32_t x1,
                       uint32_t* o0, uint32_t* o1) {
    uint32_t ks[3] = {K1, K2, K1 ^ K2 ^ 0x1BD11BDAu};
    static const int rots[2][4] = {{13,15,26,6},{17,29,16,24}};
    x0 += ks[0]; x1 += ks[1];
    for (int g = 0; g < 5; ++g) {
        const int* rr = rots[g & 1];
        for (int j = 0; j < 4; ++j) { x0 += x1; x1 = h_rotl(x1, rr[j]); x1 ^= x0; }
        x0 += ks[(g + 1) % 3];
        x1 += ks[(g + 2) % 3] + (uint32_t)(g + 1);
    }
    *o0 = x0; *o1 = x1;
}

// ---------------- helpers ----------------
__device__ __forceinline__ float4 leaky4(float4 h) {
    h.x = h.x >= 0.f ? h.x : 0.5f * h.x;
    h.y = h.y >= 0.f ? h.y : 0.5f * h.y;
    h.z = h.z >= 0.f ? h.z : 0.5f * h.z;
    h.w = h.w >= 0.f ? h.w : 0.5f * h.w;
    return h;
}
__device__ __forceinline__ float4 add4(float4 a, float4 b) {
    return make_float4(a.x + b.x, a.y + b.y, a.z + b.z, a.w + b.w);
}

// ---------------- sort pipeline ----------------
__global__ void hist_kernel(const int* __restrict__ ar,
                            const int* __restrict__ tr,
                            const int* __restrict__ sr) {
    unsigned tid = blockIdx.x * TB + threadIdx.x;      // < ETOT
    unsigned bin;
    if (tid < EADJ)               bin = (unsigned)__ldg(ar + tid);
    else if (tid < EADJ + ETAG)   bin = NADJ + (unsigned)__ldg(tr + (tid - EADJ));
    else                          bin = SOC_BIN0 + (unsigned)__ldg(sr + (tid - EADJ - ETAG));
    atomicAdd(&((uint32_t*)g_bins4)[bin], 1u);
}

// block-level exclusive scan over 1024 bins, write partials + block total
__global__ void scanA_kernel() {
    unsigned t = threadIdx.x, b = blockIdx.x;
    uint4 v = g_bins4[b * 256 + t];
    uint32_t sum = v.x + v.y + v.z + v.w;
    uint32_t incl = sum;
#pragma unroll
    for (int d = 1; d < 32; d <<= 1) {
        uint32_t n = __shfl_up_sync(0xffffffffu, incl, d);
        if ((t & 31u) >= (unsigned)d) incl += n;
    }
    __shared__ uint32_t ws[8], wo[8];
    if ((t & 31u) == 31u) ws[t >> 5] = incl;
    __syncthreads();
    if (t == 0) {
        uint32_t run = 0;
#pragma unroll
        for (int i = 0; i < 8; ++i) { wo[i] = run; run += ws[i]; }
        g_blkSum[b] = run;
    }
    __syncthreads();
    uint32_t excl = incl - sum + wo[t >> 5];
    uint4 o;
    o.x = excl; o.y = excl + v.x; o.z = o.y + v.y; o.w = o.z + v.z;
    g_binScan4[b * 256 + t] = o;
}

// scan the 313 block totals (single block)
__global__ void scanB_kernel() {
    unsigned t = threadIdx.x;                 // 512 threads
    uint32_t sum = (t < SCANB) ? g_blkSum[t] : 0u;
    uint32_t incl = sum;
#pragma unroll
    for (int d = 1; d < 32; d <<= 1) {
        uint32_t n = __shfl_up_sync(0xffffffffu, incl, d);
        if ((t & 31u) >= (unsigned)d) incl += n;
    }
    __shared__ uint32_t ws[16], wo[16];
    if ((t & 31u) == 31u) ws[t >> 5] = incl;
    __syncthreads();
    if (t == 0) {
        uint32_t run = 0;
#pragma unroll
        for (int i = 0; i < 16; ++i) { wo[i] = run; run += ws[i]; }
    }
    __syncthreads();
    if (t < SCANB) g_blkOff[t] = incl - sum + wo[t >> 5];
}

// finalize global bin starts (+64 shift for soc region padding)
__global__ void scanC_kernel() {
    unsigned t = threadIdx.x, b = blockIdx.x;
    unsigned idx4 = b * 256 + t;
    uint32_t add = g_blkOff[b] + ((idx4 >= SOC_BIN0 / 4) ? 64u : 0u);
    uint4 v = g_binScan4[idx4];
    v.x += add; v.y += add; v.z += add; v.w += add;
    g_binScan4[idx4] = v;
}

// scatter edges into row-sorted order; also re-zero the histogram bins
__global__ void scatter_kernel(const int* __restrict__ ar, const int* __restrict__ ac,
                               const float* __restrict__ av,
                               const int* __restrict__ tr, const int* __restrict__ tc,
                               const float* __restrict__ tv,
                               const int* __restrict__ sr, const int* __restrict__ sc,
                               const float* __restrict__ sv) {
    unsigned tid = blockIdx.x * TB + threadIdx.x;      // < ETOT
    unsigned e, bin; int r, c; float v;
    if (tid < EADJ) {
        e = tid;               r = __ldg(ar + e); c = __ldg(ac + e); v = __ldg(av + e); bin = (unsigned)r;
    } else if (tid < EADJ + ETAG) {
        e = tid - EADJ;        r = __ldg(tr + e); c = __ldg(tc + e); v = __ldg(tv + e); bin = NADJ + (unsigned)r;
    } else {
        e = tid - EADJ - ETAG; r = __ldg(sr + e); c = __ldg(sc + e); v = __ldg(sv + e); bin = SOC_BIN0 + (unsigned)r;
    }
    unsigned pos = atomicAdd(&((uint32_t*)g_binScan4)[bin], 1u);
    g_sorted[pos] = make_uint4((unsigned)r, (unsigned)c, __float_as_uint(v), e);
    // restore g_bins to zero (zero-on-exit invariant); scanA already consumed it
    if (tid < NBINP) ((uint32_t*)g_bins4)[tid] = 0u;
}

// ---------------- fused mask + row-sorted SPMM with register aggregation --------
// Warp = 16 consecutive sorted edges (2 slots x 8). Lanes 0..15 load one record
// each + compute its threefry mask; shuffles distribute to slots. Each slot
// gathers its 8 edges (MLP) then combines same-row runs in registers before RED.
template <int LAYER>
__global__ void spmm_kernel(const float4* __restrict__ u4,
                            const float4* __restrict__ i4,
                            const float4* __restrict__ t4,
                            uint32_t ka1, uint32_t ka2, uint32_t kt1, uint32_t kt2,
                            uint32_t ku1, uint32_t ku2) {
    unsigned bid = blockIdx.x;
    float4* outb; int mode; uint32_t k1, k2;
    if (bid < A_SBLK)                { outb = g_tem;       mode = 0; k1 = ka1; k2 = ka2; }
    else if (bid < A_SBLK + T_SBLK)  { outb = g_tg[LAYER]; mode = 1; k1 = kt1; k2 = kt2; }
    else                             { outb = g_soc;       mode = 2; k1 = ku1; k2 = ku2; }
    unsigned lane  = threadIdx.x & 31u;
    unsigned warp  = threadIdx.x >> 5;
    unsigned chunk = lane & 15u;
    unsigned slot  = lane >> 4;
    unsigned wbase = bid * EPB + warp * 16u;

    // each lane loads one record (lanes 16..31 mirror 0..15 -> broadcast hit)
    uint4 rec = __ldg(&g_sorted[wbase + (lane & 15u)]);
    // inline dropout mask on the original edge index (rec.w); pads have val=0
    uint32_t bits = tf_bits(k1, k2, rec.w);
    float u    = __uint_as_float((bits >> 9) | 0x3f800000u) - 1.0f;
    float mval = (__uint_as_float(rec.z) * floorf(u + 0.9f)) * (float)(1.0 / 0.9);

    // distribute: slot s, pos i -> source lane 8*s + i (consecutive edges)
    float v[NE]; int rr[NE], cc[NE];
#pragma unroll
    for (int i = 0; i < NE; ++i) {
        int j = 8 * (int)slot + i;
        v[i]  = __shfl_sync(0xffffffffu, mval,       j);
        rr[i] = __shfl_sync(0xffffffffu, (int)rec.x, j);
        cc[i] = __shfl_sync(0xffffffffu, (int)rec.y, j);
    }
    // MLP-batched gathers (skip dropped/padding edges -> saves LTS bytes)
    float4 xv[NE];
#pragma unroll
    for (int i = 0; i < NE; ++i) {
        if (v[i] != 0.f) {
            int c = cc[i];
            const float4* x;
            if (LAYER == 0) {
                if (mode == 1)
                    x = (c < ITEM_N) ? (i4 + (unsigned)c * R4)
                                     : (t4 + (unsigned)(c - ITEM_N) * R4);
                else
                    x = (c < USER_N) ? (u4 + (unsigned)c * R4)
                                     : (i4 + (unsigned)(c - USER_N) * R4);
            } else {
                if (mode == 1)
                    x = (c < ITEM_N) ? (g_lat + (unsigned)(USER_N + c) * R4)
                                     : (g_taglat + (unsigned)c * R4);
                else
                    x = g_lat + (unsigned)c * R4;
            }
            xv[i] = __ldg(x + chunk);
        }
    }
    // register aggregation over same-row runs (slot-uniform predicates)
    int   cur = rr[0];
    float4 acc = make_float4(0.f, 0.f, 0.f, 0.f);
    bool touched = false;
#pragma unroll
    for (int i = 0; i < NE; ++i) {
        if (rr[i] != cur) {
            if (touched) {
                float4* dst = outb + (unsigned)cur * R4 + chunk;
                asm volatile("red.global.add.v4.f32 [%0], {%1,%2,%3,%4};"
                             :: "l"(dst), "f"(acc.x), "f"(acc.y), "f"(acc.z), "f"(acc.w)
                             : "memory");
            }
            cur = rr[i]; acc = make_float4(0.f, 0.f, 0.f, 0.f); touched = false;
        }
        if (v[i] != 0.f) {
            acc.x += v[i] * xv[i].x; acc.y += v[i] * xv[i].y;
            acc.z += v[i] * xv[i].z; acc.w += v[i] * xv[i].w;
            touched = true;
        }
    }
    if (touched) {
        float4* dst = outb + (unsigned)cur * R4 + chunk;
        asm volatile("red.global.add.v4.f32 [%0], {%1,%2,%3,%4};"
                     :: "l"(dst), "f"(acc.x), "f"(acc.y), "f"(acc.z), "f"(acc.w)
                     : "memory");
    }
}

// combine-mid: lat = leaky(tem)+leaky(soc|tg0); taglat(tag part) = leaky(tg0);
// zero tem + soc. All loads before all stores.
__global__ void mid_kernel() {
    const float4 z = make_float4(0.f, 0.f, 0.f, 0.f);
    unsigned base = blockIdx.x * (2u * TB) + threadIdx.x;
    unsigned ia = base, ib = base + TB;
    bool va = ia < NELEM, vb = ib < NELEM;
    unsigned a = va ? ia : 0u, b = vb ? ib : 0u;
    bool ua = a < UELEM, ub = b < UELEM;
    bool ga = (a >= IELEM) & (a < GELEM);
    bool gb = (b >= IELEM) & (b < GELEM);
    float4 ta  = g_tem[a];
    float4 tb4 = g_tem[b];
    float4 sa  = ua ? g_soc[a] : g_tg[0][a - UELEM];
    float4 sb  = ub ? g_soc[b] : g_tg[0][b - UELEM];
    float4 g0a = ga ? g_tg[0][a] : z;
    float4 g0b = gb ? g_tg[0][b] : z;
    float4 oa = add4(leaky4(ta),  leaky4(sa));
    float4 ob = add4(leaky4(tb4), leaky4(sb));
    if (va) {
        g_lat[a] = oa; g_tem[a] = z;
        if (ua) g_soc[a] = z;
        if (ga) g_taglat[a] = leaky4(g0a);
    }
    if (vb) {
        g_lat[b] = ob; g_tem[b] = z;
        if (ub) g_soc[b] = z;
        if (gb) g_taglat[b] = leaky4(g0b);
    }
}

// combine-final: out = (u|i) + g_lat + leaky(tem) + leaky(soc|tg1); re-zero state.
__global__ void fin_kernel(float4* __restrict__ out,
                           const float4* __restrict__ u4,
                           const float4* __restrict__ i4) {
    const float4 z = make_float4(0.f, 0.f, 0.f, 0.f);
    unsigned base = blockIdx.x * (2u * TB) + threadIdx.x;
    unsigned ia = base, ib = base + TB;
    bool va = ia < NELEM, vb = ib < NELEM;
    unsigned a = va ? ia : 0u, b = vb ? ib : 0u;
    bool ua = a < UELEM, ub = b < UELEM;
    float4 ta  = g_tem[a];
    float4 tb4 = g_tem[b];
    float4 sa  = ua ? g_soc[a] : g_tg[1][a - UELEM];
    float4 sb  = ub ? g_soc[b] : g_tg[1][b - UELEM];
    float4 la  = g_lat[a];
    float4 lb  = g_lat[b];
    float4 ea  = ua ? __ldg(u4 + a) : __ldg(i4 + a - UELEM);
    float4 eb  = ub ? __ldg(u4 + b) : __ldg(i4 + b - UELEM);
    float4 l2a = add4(leaky4(ta),  leaky4(sa));
    float4 l2b = add4(leaky4(tb4), leaky4(sb));
    if (va) {
        out[a] = add4(add4(ea, la), l2a);
        g_tem[a] = z;
        if (ua) g_soc[a] = z; else g_tg[1][a - UELEM] = z;
    }
    if (vb) {
        out[b] = add4(add4(eb, lb), l2b);
        g_tem[b] = z;
        if (ub) g_soc[b] = z; else g_tg[1][b - UELEM] = z;
    }
    // zero buffers nobody reads here: all of tg[0], tg[1] tag tail
    const unsigned NTHR = (unsigned)COMBB * TB;
    unsigned gt = blockIdx.x * TB + threadIdx.x;
    for (unsigned k = gt; k < GELEM + TELEM; k += NTHR) {
        if (k < GELEM) g_tg[0][k] = z;
        else           g_tg[1][IELEM + (k - GELEM)] = z;
    }
}

// ---------------- launch ----------------
extern "C" void kernel_launch(void* const* d_in, const int* in_sizes, int n_in,
                              void* d_out, int out_size) {
    const float4* uE = (const float4*)d_in[0];
    const float4* iE = (const float4*)d_in[1];
    const float4* tE = (const float4*)d_in[2];
    const int*   ar = (const int*)d_in[3];
    const int*   ac = (const int*)d_in[4];
    const float* av = (const float*)d_in[5];
    const int*   tr = (const int*)d_in[6];
    const int*   tc = (const int*)d_in[7];
    const float* tv = (const float*)d_in[8];
    const int*   sr = (const int*)d_in[9];
    const int*   sc = (const int*)d_in[10];
    const float* sv = (const float*)d_in[11];
    float4* out = (float4*)d_out;

    // jax.random.key(42) -> (0, 42); fold_in(key, j) = threefry2x32(key, (0, j))
    uint32_t fk[6][2];
    for (uint32_t j = 0; j < 6; ++j)
        h_threefry(0u, 42u, 0u, j, &fk[j][0], &fk[j][1]);

    // row-sort the edge lists (shared by both layers)
    hist_kernel<<<EB, TB>>>(ar, tr, sr);
    scanA_kernel<<<SCANB, 256>>>();
    scanB_kernel<<<1, 512>>>();
    scanC_kernel<<<SCANB, 256>>>();
    scatter_kernel<<<EB, TB>>>(ar, ac, av, tr, tc, tv, sr, sc, sv);

    // layer 0: fused mask+spmm from input embeddings
    spmm_kernel<0><<<SPMMB, TB>>>(uE, iE, tE,
                                  fk[0][0], fk[0][1], fk[1][0], fk[1][1],
                                  fk[2][0], fk[2][1]);
    mid_kernel<<<COMBB, TB>>>();
    // layer 1: fused mask+spmm from g_lat / g_taglat
    spmm_kernel<1><<<SPMMB, TB>>>(uE, iE, tE,
                                  fk[3][0], fk[3][1], fk[4][0], fk[4][1],
                                  fk[5][0], fk[5][1]);
    fin_kernel<<<COMBB, TB>>>(out, uE, iE);
}